// round 13
// baseline (speedup 1.0000x reference)
#include <cuda_runtime.h>
#include <cuda_bf16.h>
#include <math.h>

// Problem constants
#define N_TOK   8192
#define DDIM    4096
#define NE      16

// Logits GEMM tiling
#define KSPLIT  16
#define KRANGE  (DDIM / KSPLIT)   // 256
#define KC      16                // K per pipeline stage
#define NITER   (KRANGE / KC)     // 16
#define TB      256               // tokens per block tile
#define XP      20                // x smem row stride (floats); conflicts fixed via K-rotation
#define WP      22                // w smem row stride (floats); 8*tx bank shift vs x rows

// Output layout (floats): [ l_aux | token_pos_after(2N) | token_pos_before(2N) | counts(E) | weight(2N) ]
#define OFF_AFTER   1
#define OFF_BEFORE  (1 + 2 * N_TOK)
#define OFF_CNT     (1 + 4 * N_TOK)
#define OFF_W       (1 + 4 * N_TOK + NE)

#define NBLK 128   // gate blocks (64 tokens each); <148 SMs: co-resident barrier OK
#define GT   512   // gate threads: 8 per token

// Scratch. Partials: [split][expert-group q][token] as float4 (lane-consecutive).
__device__ float    g_partial[KSPLIT][4][(size_t)N_TOK * 4];   // 8 MB
__device__ int      g_h1[NBLK][NE];
__device__ int      g_h2[NBLK][NE];
__device__ float    g_colsum_part[NBLK][NE];
__device__ unsigned g_bar;   // ticket barrier (never reset; 2^32 % NBLK == 0)

__device__ __forceinline__ void cpa16(void* dst, const void* src) {
    unsigned d = (unsigned)__cvta_generic_to_shared(dst);
    asm volatile("cp.async.cg.shared.global [%0], [%1], 16;" :: "r"(d), "l"(src));
}
__device__ __forceinline__ void cpa8(void* dst, const void* src) {
    unsigned d = (unsigned)__cvta_generic_to_shared(dst);
    asm volatile("cp.async.ca.shared.global [%0], [%1], 8;" :: "r"(d), "l"(src));
}

// ---------------------------------------------------------------------------
// Kernel 1: logits partials.  grid = (32 token tiles, 16 K-splits), 64 thr.
// Micro-tile: 8 tokens x 8 experts (f32x2).  Bank conflicts eliminated by
// per-thread K rotation kp=(kk+(ty>>3))&7 (x banks get parity split) and
// WP=22 for w (tx halves shifted 8 banks).  Rotation only permutes the
// per-thread K summation order (deterministic).
// ---------------------------------------------------------------------------
__global__ __launch_bounds__(64) void logits_kernel(
    const float* __restrict__ x, const float* __restrict__ wg)
{
    __shared__ float xs[2][TB][XP];   // 40960 B
    __shared__ float ws[2][NE][WP];   //  2816 B

    const int tid     = threadIdx.x;
    const int tx      = tid & 1;      // expert half: experts tx*8 .. tx*8+7
    const int ty      = tid >> 1;     // token slot: tokens ty + 32*r, r=0..7
    const int rot     = (ty >> 3) & 1;
    const int tokBase = blockIdx.x * TB;
    const int kBase0  = blockIdx.y * KRANGE;

    auto load_stage = [&](int c, int buf) {
        const int kb = kBase0 + c * KC;
        // x tile: 256 rows x 16 floats = 1024 float4, 16 per thread
#pragma unroll
        for (int p = 0; p < 16; p++) {
            int id  = tid + p * 64;
            int row = id >> 2, col = (id & 3) * 4;
            cpa16(&xs[buf][row][col], &x[(size_t)(tokBase + row) * DDIM + kb + col]);
        }
        // w tile: 16 rows x 16 floats = 128 8B chunks, 2 per thread
#pragma unroll
        for (int h = 0; h < 2; h++) {
            int cidx = tid * 2 + h;
            int row = cidx >> 3, col = (cidx & 7) * 2;
            cpa8(&ws[buf][row][col], &wg[(size_t)row * DDIM + kb + col]);
        }
        asm volatile("cp.async.commit_group;");
    };

    unsigned long long acc[64];       // [r][j]: 8 tokens x 8 experts, f32x2
#pragma unroll
    for (int i = 0; i < 64; i++) acc[i] = 0ull;

    load_stage(0, 0);

    for (int c = 0; c < NITER; c++) {
        const int buf = c & 1;
        asm volatile("cp.async.wait_group 0;");
        __syncthreads();   // publish stage c; iter c-1 reads of buf^1 complete
        if (c + 1 < NITER) load_stage(c + 1, buf ^ 1);

#pragma unroll
        for (int kk = 0; kk < KC / 2; kk++) {
            const int kp = (kk + rot) & 7;    // rotated K-pair (bank parity split)
            unsigned long long w2[8], x2[8];
#pragma unroll
            for (int j = 0; j < 8; j++)
                w2[j] = *(const unsigned long long*)&ws[buf][tx * 8 + j][kp * 2];
#pragma unroll
            for (int r = 0; r < 8; r++)
                x2[r] = *(const unsigned long long*)&xs[buf][ty + r * 32][kp * 2];
#pragma unroll
            for (int r = 0; r < 8; r++)
#pragma unroll
                for (int j = 0; j < 8; j++)
                    asm("fma.rn.f32x2 %0, %1, %2, %0;"
                        : "+l"(acc[r * 8 + j]) : "l"(x2[r]), "l"(w2[j]));
        }
    }

    // Write partials: per token, 2 float4s (expert groups q = 2*tx, 2*tx+1)
#pragma unroll
    for (int r = 0; r < 8; r++) {
        const int tok = tokBase + ty + r * 32;
#pragma unroll
        for (int h = 0; h < 2; h++) {
            float4 v;
            float* vp = (float*)&v;
#pragma unroll
            for (int j = 0; j < 4; j++) {
                unsigned long long a = acc[r * 8 + h * 4 + j];
                float lo = __uint_as_float((unsigned)(a & 0xffffffffull));
                float hi = __uint_as_float((unsigned)(a >> 32));
                vp[j] = lo + hi;
            }
            *(float4*)&g_partial[blockIdx.y][2 * tx + h][(size_t)tok * 4] = v;
        }
    }
}

// ---------------------------------------------------------------------------
// Kernel 2 (fused): 8 threads/token DRAM-saturating reduce + softmax + top-2 +
// weights + ranks, grid barrier, scan + offsets + counts + l_aux + scatter.
// grid = 128 x 512 (64 tokens per block).
// ---------------------------------------------------------------------------
__global__ __launch_bounds__(GT) void gate_fused_kernel(float* __restrict__ out)
{
    __shared__ float ls[64][17];      // reduced logits per token (pad 17: CF)
    __shared__ int   wh1[2][NE], wh2[2][NE];
    __shared__ int   pre1[2][NE], pre2[2][NE];
    __shared__ float warp_sums[2][NE];
    __shared__ int   sb1[NE], sb2[NE], tot_s[NE], cnt1_s[NE];
    __shared__ float me_part[NE];

    const int tid  = threadIdx.x;
    const int lane = tid & 31;
    const int warp = tid >> 5;
    const int blk  = blockIdx.x;

    // ---- Phase A: 8 threads per token; 8 batched float4 loads per thread ----
    {
        const int tkn = tid >> 3;         // 0..63
        const int pc  = tid & 7;          // piece: splits 2*pc, 2*pc+1
        const int tt  = blk * 64 + tkn;
        float4 v0[4], v1[4];
#pragma unroll
        for (int q = 0; q < 4; q++)
            v0[q] = *(const float4*)&g_partial[2 * pc][q][(size_t)tt * 4];
#pragma unroll
        for (int q = 0; q < 4; q++)
            v1[q] = *(const float4*)&g_partial[2 * pc + 1][q][(size_t)tt * 4];
        float4 a[4];
#pragma unroll
        for (int q = 0; q < 4; q++) {
            a[q].x = v0[q].x + v1[q].x; a[q].y = v0[q].y + v1[q].y;
            a[q].z = v0[q].z + v1[q].z; a[q].w = v0[q].w + v1[q].w;
        }
        // butterfly over the 8 lanes holding this token (lanes pc^1, pc^2, pc^4)
#pragma unroll
        for (int off = 1; off <= 4; off <<= 1) {
#pragma unroll
            for (int q = 0; q < 4; q++) {
                a[q].x += __shfl_xor_sync(0xffffffffu, a[q].x, off);
                a[q].y += __shfl_xor_sync(0xffffffffu, a[q].y, off);
                a[q].z += __shfl_xor_sync(0xffffffffu, a[q].z, off);
                a[q].w += __shfl_xor_sync(0xffffffffu, a[q].w, off);
            }
        }
        if (pc == 0) {
#pragma unroll
            for (int q = 0; q < 4; q++) {
                ls[tkn][q * 4 + 0] = a[q].x; ls[tkn][q * 4 + 1] = a[q].y;
                ls[tkn][q * 4 + 2] = a[q].z; ls[tkn][q * 4 + 3] = a[q].w;
            }
        }
    }
    if (tid < 32) { ((int*)wh1)[tid] = 0; ((int*)wh2)[tid] = 0; }
    __syncthreads();

    // ---- Scalar epilogue on tid<64 (one thread per token) ----
    const int t = blk * 64 + tid;     // valid for tid<64
    int e1 = 0, e2 = 0;
    float p[NE], sum = 0.0f;
    if (tid < 64) {
        float l[NE];
#pragma unroll
        for (int e = 0; e < NE; e++) l[e] = ls[tid][e];
        float m = l[0];
#pragma unroll
        for (int e = 1; e < NE; e++) m = fmaxf(m, l[e]);
#pragma unroll
        for (int e = 0; e < NE; e++) { p[e] = expf(l[e] - m); sum += p[e]; }

        // top-2 (strict > keeps lowest index, matching lax.top_k ties)
        float b1 = l[0];
#pragma unroll
        for (int e = 1; e < NE; e++) if (l[e] > b1) { b1 = l[e]; e1 = e; }
        float b2 = -3.4e38f; e2 = -1;
#pragma unroll
        for (int e = 0; e < NE; e++) if (e != e1 && l[e] > b2) { b2 = l[e]; e2 = e; }

        float p1 = p[e1], p2 = p[e2];
        float invn = 1.0f / (p1 + p2);
        out[OFF_W + t]         = p1 * invn;
        out[OFF_W + N_TOK + t] = p2 * invn;
    }

    // per-warp expert histograms + in-warp ranks (warps 0,1 fully active)
    int lr1 = 0, lr2 = 0;
    if (tid < 64) {
        unsigned m1 = __match_any_sync(0xffffffffu, e1);
        lr1 = __popc(m1 & ((1u << lane) - 1u));
        if ((__ffs(m1) - 1) == lane) wh1[warp][e1] = __popc(m1);
        unsigned m2 = __match_any_sync(0xffffffffu, e2);
        lr2 = __popc(m2 & ((1u << lane) - 1u));
        if ((__ffs(m2) - 1) == lane) wh2[warp][e2] = __popc(m2);
    }
    __syncthreads();

    if (tid < NE) {
        int r = wh1[0][tid];
        pre1[0][tid] = 0; pre1[1][tid] = r;
        g_h1[blk][tid] = r + wh1[1][tid];
        r = wh2[0][tid];
        pre2[0][tid] = 0; pre2[1][tid] = r;
        g_h2[blk][tid] = r + wh2[1][tid];
    }
    __syncthreads();

    int r1 = 0, r2 = 0;
    if (tid < 64) {
        r1 = pre1[warp][e1] + lr1;    // in-block rank, < 64
        r2 = pre2[warp][e2] + lr2;
        // deterministic per-block gate column sums (for l_aux's me)
        float invs = 1.0f / sum;
#pragma unroll
        for (int e = 0; e < NE; e++) {
            float g = p[e] * invs;
#pragma unroll
            for (int off = 16; off > 0; off >>= 1)
                g += __shfl_xor_sync(0xffffffffu, g, off);
            if (lane == 0) warp_sums[warp][e] = g;
        }
    }
    __syncthreads();
    if (tid < NE) g_colsum_part[blk][tid] = warp_sums[0][tid] + warp_sums[1][tid];

    // ---- Grid barrier (ticket-based, replay-safe) ----
    __threadfence();
    __syncthreads();
    if (tid == 0) {
        unsigned ticket = atomicAdd(&g_bar, 1u);
        unsigned target = ticket - (ticket % NBLK) + NBLK;
        while (atomicAdd(&g_bar, 0u) < target) __nanosleep(64);
    }
    __syncthreads();
    __threadfence();     // acquire

    // ---- Phase B: decomposed scan (unrolled -> loads batch) ----
    if (tid < NE) {
        const int e = tid;
        int s = 0, my1 = 0, my2 = 0;
#pragma unroll
        for (int bb = 0; bb < NBLK; bb++) { if (bb == blk) my1 = s; s += g_h1[bb][e]; }
        cnt1_s[e] = s;                         // top-1 counts (ce numerator)
#pragma unroll
        for (int bb = 0; bb < NBLK; bb++) { if (bb == blk) my2 = s; s += g_h2[bb][e]; }
        tot_s[e] = s;
        sb1[e] = my1; sb2[e] = my2;
        float me = 0.0f;
#pragma unroll
        for (int bb = 0; bb < NBLK; bb++) me += g_colsum_part[bb][e];
        me_part[e] = me;
    }
    __syncthreads();
    if (tid < NE) {
        int o = 0;
        for (int q = 0; q < tid; q++) o += tot_s[q];   // exclusive expert offset
        sb1[tid] += o; sb2[tid] += o;
        if (blk == 0) out[OFF_CNT + tid] = (float)tot_s[tid];
    }
    __syncthreads();

    // ---- Scatter ----
    if (tid < 64) {
        const int a1 = sb1[e1] + r1;
        const int a2 = sb2[e2] + r2;
        out[OFF_AFTER + t]         = (float)a1;
        out[OFF_AFTER + N_TOK + t] = (float)a2;
        out[OFF_BEFORE + a1]       = (float)t;        // permutation -> fills all
        out[OFF_BEFORE + a2]       = (float)(N_TOK + t);
    }

    // ---- l_aux ----
    if (blk == 0 && tid == 0) {
        float laux = 0.0f;
        for (int q = 0; q < NE; q++)
            laux += (me_part[q] / (float)N_TOK) * ((float)cnt1_s[q] / (float)N_TOK);
        out[0] = laux * (float)NE;
    }
}

// ---------------------------------------------------------------------------
extern "C" void kernel_launch(void* const* d_in, const int* in_sizes, int n_in,
                              void* d_out, int out_size)
{
    const float* x  = (const float*)d_in[0];   // [8192, 4096] f32
    const float* wg = (const float*)d_in[1];   // [16, 4096] f32
    float* out = (float*)d_out;

    dim3 lgrid(N_TOK / TB, KSPLIT);            // (32, 16) = 512 CTAs
    logits_kernel<<<lgrid, 64>>>(x, wg);
    gate_fused_kernel<<<NBLK, GT>>>(out);
}

// round 14
// speedup vs baseline: 1.2870x; 1.2870x over previous
#include <cuda_runtime.h>
#include <cuda_bf16.h>
#include <math.h>

// Problem constants
#define N_TOK   8192
#define DDIM    4096
#define NE      16

// Logits GEMM tiling
#define KSPLIT  16
#define KRANGE  (DDIM / KSPLIT)   // 256
#define KC      16                // K per pipeline stage
#define NITER   (KRANGE / KC)     // 16
#define TB      256               // tokens per block tile
#define XP      20                // x smem row stride (floats)
#define WP      22                // w smem row stride (floats)

// Output layout (floats): [ l_aux | token_pos_after(2N) | token_pos_before(2N) | counts(E) | weight(2N) ]
#define OFF_AFTER   1
#define OFF_BEFORE  (1 + 2 * N_TOK)
#define OFF_CNT     (1 + 4 * N_TOK)
#define OFF_W       (1 + 4 * N_TOK + NE)

#define NBLK 32   // gate/scatter blocks of 256 tokens

// Scratch (device globals). Token-major partials: coalesced on both sides.
__device__ float g_partial[KSPLIT][(size_t)N_TOK * NE];   // 8 MB
__device__ int   g_info[N_TOK];          // packed e1|r1|e2|r2
__device__ int   g_h1[NBLK][NE];
__device__ int   g_h2[NBLK][NE];
__device__ float g_colsum_part[NBLK][NE];

__device__ __forceinline__ void cpa16(void* dst, const void* src) {
    unsigned d = (unsigned)__cvta_generic_to_shared(dst);
    asm volatile("cp.async.cg.shared.global [%0], [%1], 16;" :: "r"(d), "l"(src));
}
__device__ __forceinline__ void cpa8(void* dst, const void* src) {
    unsigned d = (unsigned)__cvta_generic_to_shared(dst);
    asm volatile("cp.async.ca.shared.global [%0], [%1], 8;" :: "r"(d), "l"(src));
}

// ---------------------------------------------------------------------------
// Kernel 1: logits partials.  grid = (32 token tiles, 16 K-splits), 64 thr.
// Micro-tile: 8 tokens x 8 experts (f32x2).  Per-thread K rotation splits
// bank parity; WP=22 shifts w halves.  (Unchanged from R13 except the
// partial store layout, now token-major.)
// ---------------------------------------------------------------------------
__global__ __launch_bounds__(64) void logits_kernel(
    const float* __restrict__ x, const float* __restrict__ wg)
{
    __shared__ float xs[2][TB][XP];   // 40960 B
    __shared__ float ws[2][NE][WP];   //  2816 B

    const int tid     = threadIdx.x;
    const int tx      = tid & 1;      // expert half: experts tx*8 .. tx*8+7
    const int ty      = tid >> 1;     // token slot: tokens ty + 32*r, r=0..7
    const int rot     = (ty >> 3) & 1;
    const int tokBase = blockIdx.x * TB;
    const int kBase0  = blockIdx.y * KRANGE;

    auto load_stage = [&](int c, int buf) {
        const int kb = kBase0 + c * KC;
#pragma unroll
        for (int p = 0; p < 16; p++) {
            int id  = tid + p * 64;
            int row = id >> 2, col = (id & 3) * 4;
            cpa16(&xs[buf][row][col], &x[(size_t)(tokBase + row) * DDIM + kb + col]);
        }
#pragma unroll
        for (int h = 0; h < 2; h++) {
            int cidx = tid * 2 + h;
            int row = cidx >> 3, col = (cidx & 7) * 2;
            cpa8(&ws[buf][row][col], &wg[(size_t)row * DDIM + kb + col]);
        }
        asm volatile("cp.async.commit_group;");
    };

    unsigned long long acc[64];       // [r][j]: 8 tokens x 8 experts, f32x2
#pragma unroll
    for (int i = 0; i < 64; i++) acc[i] = 0ull;

    load_stage(0, 0);

    for (int c = 0; c < NITER; c++) {
        const int buf = c & 1;
        asm volatile("cp.async.wait_group 0;");
        __syncthreads();
        if (c + 1 < NITER) load_stage(c + 1, buf ^ 1);

#pragma unroll
        for (int kk = 0; kk < KC / 2; kk++) {
            const int kp = (kk + rot) & 7;
            unsigned long long w2[8], x2[8];
#pragma unroll
            for (int j = 0; j < 8; j++)
                w2[j] = *(const unsigned long long*)&ws[buf][tx * 8 + j][kp * 2];
#pragma unroll
            for (int r = 0; r < 8; r++)
                x2[r] = *(const unsigned long long*)&xs[buf][ty + r * 32][kp * 2];
#pragma unroll
            for (int r = 0; r < 8; r++)
#pragma unroll
                for (int j = 0; j < 8; j++)
                    asm("fma.rn.f32x2 %0, %1, %2, %0;"
                        : "+l"(acc[r * 8 + j]) : "l"(x2[r]), "l"(w2[j]));
        }
    }

    // Write partials token-major: 2 float4s per token (experts tx*8 .. tx*8+7)
#pragma unroll
    for (int r = 0; r < 8; r++) {
        const int tok = tokBase + ty + r * 32;
#pragma unroll
        for (int h = 0; h < 2; h++) {
            float4 v;
            float* vp = (float*)&v;
#pragma unroll
            for (int j = 0; j < 4; j++) {
                unsigned long long a = acc[r * 8 + h * 4 + j];
                float lo = __uint_as_float((unsigned)(a & 0xffffffffull));
                float hi = __uint_as_float((unsigned)(a >> 32));
                vp[j] = lo + hi;
            }
            *(float4*)&g_partial[blockIdx.y][(size_t)tok * NE + tx * 8 + h * 4] = v;
        }
    }
}

// ---------------------------------------------------------------------------
// Kernel 2: gate — reduce partials, softmax, top-2, weights, per-block
// histograms + in-block ranks + colsums.  grid = 32 x 256 (1 thread/token).
// No grid barrier.
// ---------------------------------------------------------------------------
__global__ __launch_bounds__(256) void gate_kernel(float* __restrict__ out_w)
{
    __shared__ int   wh1[8][NE], wh2[8][NE];
    __shared__ int   pre1[8][NE], pre2[8][NE];
    __shared__ float warp_sums[8][NE];

    const int tid  = threadIdx.x;
    const int lane = tid & 31;
    const int warp = tid >> 5;
    const int blk  = blockIdx.x;
    const int t    = blk * 256 + tid;

    // Phase A: coalesced token-major reduce (4 independent float4 chains)
    float4 a0 = make_float4(0.f,0.f,0.f,0.f), a1 = a0, a2 = a0, a3 = a0;
#pragma unroll
    for (int s = 0; s < KSPLIT; s++) {
        const float4* base = (const float4*)&g_partial[s][(size_t)t * NE];
        float4 v0 = base[0], v1 = base[1], v2 = base[2], v3 = base[3];
        a0.x += v0.x; a0.y += v0.y; a0.z += v0.z; a0.w += v0.w;
        a1.x += v1.x; a1.y += v1.y; a1.z += v1.z; a1.w += v1.w;
        a2.x += v2.x; a2.y += v2.y; a2.z += v2.z; a2.w += v2.w;
        a3.x += v3.x; a3.y += v3.y; a3.z += v3.z; a3.w += v3.w;
    }
    float l[NE] = { a0.x,a0.y,a0.z,a0.w, a1.x,a1.y,a1.z,a1.w,
                    a2.x,a2.y,a2.z,a2.w, a3.x,a3.y,a3.z,a3.w };

    // softmax
    float m = l[0];
#pragma unroll
    for (int e = 1; e < NE; e++) m = fmaxf(m, l[e]);
    float p[NE], sum = 0.0f;
#pragma unroll
    for (int e = 0; e < NE; e++) { p[e] = expf(l[e] - m); sum += p[e]; }

    // top-2 (strict > keeps lowest index, matching lax.top_k ties)
    int e1 = 0; float b1 = l[0];
#pragma unroll
    for (int e = 1; e < NE; e++) if (l[e] > b1) { b1 = l[e]; e1 = e; }
    int e2 = -1; float b2 = -3.4e38f;
#pragma unroll
    for (int e = 0; e < NE; e++) if (e != e1 && l[e] > b2) { b2 = l[e]; e2 = e; }

    float p1 = p[e1], p2 = p[e2];
    float invn = 1.0f / (p1 + p2);
    out_w[t]         = p1 * invn;
    out_w[N_TOK + t] = p2 * invn;

    // per-warp expert histograms + in-warp ranks (order-preserving)
    if (tid < 128) { ((int*)wh1)[tid] = 0; ((int*)wh2)[tid] = 0; }
    __syncthreads();

    unsigned m1  = __match_any_sync(0xffffffffu, e1);
    int      lr1 = __popc(m1 & ((1u << lane) - 1u));
    if ((__ffs(m1) - 1) == lane) wh1[warp][e1] = __popc(m1);
    unsigned m2  = __match_any_sync(0xffffffffu, e2);
    int      lr2 = __popc(m2 & ((1u << lane) - 1u));
    if ((__ffs(m2) - 1) == lane) wh2[warp][e2] = __popc(m2);
    __syncthreads();

    if (tid < NE) {
        int r = 0;
#pragma unroll
        for (int w = 0; w < 8; w++) { pre1[w][tid] = r; r += wh1[w][tid]; }
        g_h1[blk][tid] = r;
        r = 0;
#pragma unroll
        for (int w = 0; w < 8; w++) { pre2[w][tid] = r; r += wh2[w][tid]; }
        g_h2[blk][tid] = r;
    }
    __syncthreads();

    const int r1 = pre1[warp][e1] + lr1;   // in-block rank, < 256
    const int r2 = pre2[warp][e2] + lr2;
    g_info[t] = e1 | (r1 << 4) | (e2 << 12) | (r2 << 16);

    // deterministic per-block gate column sums (for l_aux's me)
    float invs = 1.0f / sum;
#pragma unroll
    for (int e = 0; e < NE; e++) {
        float g = p[e] * invs;
#pragma unroll
        for (int off = 16; off > 0; off >>= 1)
            g += __shfl_xor_sync(0xffffffffu, g, off);
        if (lane == 0) warp_sums[warp][e] = g;
    }
    __syncthreads();
    if (tid < NE) {
        float s2 = 0.0f;
#pragma unroll
        for (int w = 0; w < 8; w++) s2 += warp_sums[w][tid];
        g_colsum_part[blk][tid] = s2;
    }
}

// ---------------------------------------------------------------------------
// Kernel 3: scatter — each block redundantly computes the tiny 32x16 scan
// (2 KB, L2-resident, fully unrolled), then scatters.  Block 0 also writes
// counts + l_aux.  grid = 32 x 256.  No grid barrier anywhere.
// ---------------------------------------------------------------------------
__global__ __launch_bounds__(256) void scatter_kernel(float* __restrict__ out)
{
    __shared__ int sb1[NE], sb2[NE], tot_s[NE], cnt1_s[NE];

    const int blk = blockIdx.x;
    const int tid = threadIdx.x;

    if (tid < NE) {
        const int e = tid;
        int s = 0, my1 = 0, my2 = 0;
#pragma unroll
        for (int bb = 0; bb < NBLK; bb++) { if (bb == blk) my1 = s; s += g_h1[bb][e]; }
        cnt1_s[e] = s;                        // top-1 counts (ce numerator)
#pragma unroll
        for (int bb = 0; bb < NBLK; bb++) { if (bb == blk) my2 = s; s += g_h2[bb][e]; }
        tot_s[e] = s;
        sb1[e] = my1; sb2[e] = my2;
    }
    __syncthreads();
    if (tid < NE) {
        int o = 0;
        for (int q = 0; q < tid; q++) o += tot_s[q];   // exclusive expert offset
        sb1[tid] += o; sb2[tid] += o;
        if (blk == 0) out[OFF_CNT + tid] = (float)tot_s[tid];
    }
    __syncthreads();

    const int t    = blk * 256 + tid;
    const int info = g_info[t];
    const int e1 = info & 15, r1 = (info >> 4) & 255;
    const int e2 = (info >> 12) & 15, r2 = (info >> 16) & 255;
    const int a1 = sb1[e1] + r1;
    const int a2 = sb2[e2] + r2;

    out[OFF_AFTER + t]         = (float)a1;
    out[OFF_AFTER + N_TOK + t] = (float)a2;
    out[OFF_BEFORE + a1]       = (float)t;            // permutation -> fills all
    out[OFF_BEFORE + a2]       = (float)(N_TOK + t);

    if (blk == 0 && tid == 0) {
        float laux = 0.0f;
        for (int q = 0; q < NE; q++) {
            float me = 0.0f;
#pragma unroll
            for (int bb = 0; bb < NBLK; bb++) me += g_colsum_part[bb][q];
            me /= (float)N_TOK;
            laux += me * ((float)cnt1_s[q] / (float)N_TOK);
        }
        out[0] = laux * (float)NE;
    }
}

// ---------------------------------------------------------------------------
extern "C" void kernel_launch(void* const* d_in, const int* in_sizes, int n_in,
                              void* d_out, int out_size)
{
    const float* x  = (const float*)d_in[0];   // [8192, 4096] f32
    const float* wg = (const float*)d_in[1];   // [16, 4096] f32
    float* out = (float*)d_out;

    dim3 lgrid(N_TOK / TB, KSPLIT);            // (32, 16) = 512 CTAs
    logits_kernel<<<lgrid, 64>>>(x, wg);
    gate_kernel<<<NBLK, 256>>>(out + OFF_W);
    scatter_kernel<<<NBLK, 256>>>(out);
}